// round 9
// baseline (speedup 1.0000x reference)
#include <cuda_runtime.h>

// out[b, t, f] = (t == (int)((1.0f - x[b,f]) * 100.0f)) ? 1.0f : 0.0f
// B=2048, T=100, F=1024. Output 839 MB -> pure HBM-store-bound.
// R9: minimum grain - TCHUNK=1, one block per (b,t) 4KB output row.
//     204800 blocks, t-fastest dense ordering, x reads L2-resident.

#define B 2048
#define T 100
#define F 1024
#define F4 (F / 4)            // 256

__global__ __launch_bounds__(256, 8)
void spike_latency_kernel(const float4* __restrict__ x, float4* __restrict__ out) {
    int bx = blockIdx.x;                 // 0 .. B*T-1, t fastest
    int b  = bx / T;                     // batch row
    int t  = bx - b * T;                 // time step
    int f4 = threadIdx.x;                // 0 .. 255

    float4 xv = __ldg(x + (size_t)b * F4 + f4);
    int s0 = (int)((1.0f - xv.x) * 100.0f);
    int s1 = (int)((1.0f - xv.y) * 100.0f);
    int s2 = (int)((1.0f - xv.z) * 100.0f);
    int s3 = (int)((1.0f - xv.w) * 100.0f);

    float4 v;
    v.x = (t == s0) ? 1.0f : 0.0f;
    v.y = (t == s1) ? 1.0f : 0.0f;
    v.z = (t == s2) ? 1.0f : 0.0f;
    v.w = (t == s3) ? 1.0f : 0.0f;
    __stcs(out + (size_t)bx * F4 + f4, v);
}

extern "C" void kernel_launch(void* const* d_in, const int* in_sizes, int n_in,
                              void* d_out, int out_size) {
    const float4* x = (const float4*)d_in[0];
    float4* out = (float4*)d_out;
    spike_latency_kernel<<<B * T, 256>>>(x, out);   // 204800 blocks
}

// round 10
// speedup vs baseline: 1.1080x; 1.1080x over previous
#include <cuda_runtime.h>

// out[b, t, f] = (t == (int)((1.0f - x[b,f]) * 100.0f)) ? 1.0f : 0.0f
// B=2048, T=100, F=1024. Output 839 MB -> pure HBM-store-bound.
// R10: grain interpolation probe TCHUNK=4 (51200 blocks, t-fastest dense
//      ordering). Grain curve so far: 25:120.8 / 10:120.9 / 5:114.7 /
//      2:113.2 / 1:127.0 us.

#define B 2048
#define T 100
#define TCHUNK 4
#define NCHUNK (T / TCHUNK)   // 25
#define F 1024
#define F4 (F / 4)            // 256

__global__ __launch_bounds__(256, 8)
void spike_latency_kernel(const float4* __restrict__ x, float4* __restrict__ out) {
    // t0-fastest block ordering: consecutive blocks share the same batch row.
    int bx = blockIdx.x;                 // 0 .. B*NCHUNK-1
    int b  = bx / NCHUNK;                // batch row
    int t0 = (bx - b * NCHUNK) * TCHUNK; // time chunk start
    int f4 = threadIdx.x;                // 0 .. 255

    float4 xv = __ldg(x + (size_t)b * F4 + f4);
    int s0 = (int)((1.0f - xv.x) * 100.0f);
    int s1 = (int)((1.0f - xv.y) * 100.0f);
    int s2 = (int)((1.0f - xv.z) * 100.0f);
    int s3 = (int)((1.0f - xv.w) * 100.0f);

    float4* po = out + (size_t)b * (T * F4) + (size_t)t0 * F4 + f4;

#pragma unroll
    for (int i = 0; i < TCHUNK; i++) {
        int t = t0 + i;
        float4 v;
        v.x = (t == s0) ? 1.0f : 0.0f;
        v.y = (t == s1) ? 1.0f : 0.0f;
        v.z = (t == s2) ? 1.0f : 0.0f;
        v.w = (t == s3) ? 1.0f : 0.0f;
        __stcs(po + (size_t)i * F4, v);   // evict-first streaming store
    }
}

extern "C" void kernel_launch(void* const* d_in, const int* in_sizes, int n_in,
                              void* d_out, int out_size) {
    const float4* x = (const float4*)d_in[0];
    float4* out = (float4*)d_out;
    spike_latency_kernel<<<B * NCHUNK, 256>>>(x, out);   // 51200 blocks
}

// round 11
// speedup vs baseline: 1.1234x; 1.0139x over previous
#include <cuda_runtime.h>

// out[b, t, f] = (t == (int)((1.0f - x[b,f]) * 100.0f)) ? 1.0f : 0.0f
// B=2048, T=100, F=1024. Output 839 MB -> pure HBM-store-bound.
// R11: R8 winner (TCHUNK=2, t-fastest dense ordering, 102400 blocks) with
//      the integer division removed via 2D grid: blockIdx.x = t-chunk
//      (fastest-varying, same dense ordering), blockIdx.y = batch row.
//      Grain curve: 25:120.8 / 10:120.9 / 5:114.7 / 4:114.6 / 2:113.2 / 1:127.0.

#define B 2048
#define T 100
#define TCHUNK 2
#define NCHUNK (T / TCHUNK)   // 50
#define F 1024
#define F4 (F / 4)            // 256

__global__ __launch_bounds__(256, 8)
void spike_latency_kernel(const float4* __restrict__ x, float4* __restrict__ out) {
    int t0 = blockIdx.x * TCHUNK;        // t-chunk: fastest-varying -> dense wave
    int b  = blockIdx.y;                 // batch row
    int f4 = threadIdx.x;                // 0 .. 255

    float4 xv = __ldg(x + (size_t)b * F4 + f4);
    int s0 = (int)((1.0f - xv.x) * 100.0f);
    int s1 = (int)((1.0f - xv.y) * 100.0f);
    int s2 = (int)((1.0f - xv.z) * 100.0f);
    int s3 = (int)((1.0f - xv.w) * 100.0f);

    float4* po = out + (size_t)b * (T * F4) + (size_t)t0 * F4 + f4;

#pragma unroll
    for (int i = 0; i < TCHUNK; i++) {
        int t = t0 + i;
        float4 v;
        v.x = (t == s0) ? 1.0f : 0.0f;
        v.y = (t == s1) ? 1.0f : 0.0f;
        v.z = (t == s2) ? 1.0f : 0.0f;
        v.w = (t == s3) ? 1.0f : 0.0f;
        __stcs(po + (size_t)i * F4, v);   // evict-first streaming store
    }
}

extern "C" void kernel_launch(void* const* d_in, const int* in_sizes, int n_in,
                              void* d_out, int out_size) {
    const float4* x = (const float4*)d_in[0];
    float4* out = (float4*)d_out;
    dim3 grid(NCHUNK, B);                // (50, 2048) = 102400 blocks
    spike_latency_kernel<<<grid, 256>>>(x, out);
}